// round 1
// baseline (speedup 1.0000x reference)
#include <cuda_runtime.h>
#include <math.h>

#define Bb 4
#define Ss 2048
#define Hh 1024
#define NH 16
#define HD 64
#define Ee 256
#define Mm (Bb*Ss)

// ---------------- scratch (static device allocations; no cudaMalloc) --------
__device__ float g_q[(size_t)Mm*Hh];      // 32 MB
__device__ float g_k[(size_t)Mm*Hh];      // 32 MB
__device__ float g_v[(size_t)Mm*Hh];      // 32 MB
__device__ float g_eq[(size_t)Mm*Ee];     // 8 MB
__device__ float g_ek[(size_t)Mm*Ee];     // 8 MB
__device__ float g_bias[(size_t)Bb*Ss*Ss];// 64 MB  (0.3*conf*(eq.ek^T)/16, shared across heads)
__device__ float g_ctx[(size_t)Mm*Hh];    // 32 MB

// ---------------- generic SGEMM: C[M,N] = A[M,K] @ W[K,N] + bias ------------
// Block 128x128, BK=8, 256 threads, 8x8 microtile. M = gridDim.x*128.
__global__ __launch_bounds__(256) void sgemm_bias(
    const float* __restrict__ A, const float* __restrict__ W,
    const float* __restrict__ bias, float* __restrict__ C,
    int N, int K)
{
    __shared__ float As[8][128];
    __shared__ float Bs[8][128];
    const int tid = threadIdx.x;
    const int tx = tid & 15, ty = tid >> 4;
    const int m0 = blockIdx.x * 128, n0 = blockIdx.y * 128;
    const int arow = tid >> 1, acol = (tid & 1) * 4;
    const int brow = tid >> 5, bcol = (tid & 31) * 4;

    float acc[8][8];
    #pragma unroll
    for (int i = 0; i < 8; i++)
        #pragma unroll
        for (int j = 0; j < 8; j++) acc[i][j] = 0.f;

    const float* Ap = A + (size_t)(m0 + arow) * K + acol;
    const float* Wp = W + (size_t)brow * N + n0 + bcol;

    for (int kt = 0; kt < K; kt += 8) {
        float4 av = *(const float4*)(Ap + kt);
        float4 bv = *(const float4*)(Wp + (size_t)kt * N);
        As[acol + 0][arow] = av.x;
        As[acol + 1][arow] = av.y;
        As[acol + 2][arow] = av.z;
        As[acol + 3][arow] = av.w;
        *(float4*)&Bs[brow][bcol] = bv;
        __syncthreads();
        #pragma unroll
        for (int k = 0; k < 8; k++) {
            float a[8], bb[8];
            *(float4*)(a)     = *(const float4*)&As[k][ty * 8];
            *(float4*)(a + 4) = *(const float4*)&As[k][ty * 8 + 4];
            *(float4*)(bb)    = *(const float4*)&Bs[k][tx * 8];
            *(float4*)(bb + 4)= *(const float4*)&Bs[k][tx * 8 + 4];
            #pragma unroll
            for (int i = 0; i < 8; i++)
                #pragma unroll
                for (int j = 0; j < 8; j++)
                    acc[i][j] += a[i] * bb[j];
        }
        __syncthreads();
    }

    #pragma unroll
    for (int i = 0; i < 8; i++) {
        const int row = m0 + ty * 8 + i;
        float4 o0, o1;
        o0.x = acc[i][0] + bias[n0 + tx * 8 + 0];
        o0.y = acc[i][1] + bias[n0 + tx * 8 + 1];
        o0.z = acc[i][2] + bias[n0 + tx * 8 + 2];
        o0.w = acc[i][3] + bias[n0 + tx * 8 + 3];
        o1.x = acc[i][4] + bias[n0 + tx * 8 + 4];
        o1.y = acc[i][5] + bias[n0 + tx * 8 + 5];
        o1.z = acc[i][6] + bias[n0 + tx * 8 + 6];
        o1.w = acc[i][7] + bias[n0 + tx * 8 + 7];
        *(float4*)&C[(size_t)row * N + n0 + tx * 8]     = o0;
        *(float4*)&C[(size_t)row * N + n0 + tx * 8 + 4] = o1;
    }
}

// ---------------- exp-bias GEMM: bias[b,i,j] = scale_b * eq[b,i,:].ek[b,j,:] -
// Both operands are [S,E] row-major -> both tiles loaded transposed.
__global__ __launch_bounds__(256) void exp_bias_gemm(const float* __restrict__ conf)
{
    const int b = blockIdx.z;
    const float* A  = g_eq + (size_t)b * Ss * Ee;
    const float* Bm = g_ek + (size_t)b * Ss * Ee;
    float* C = g_bias + (size_t)b * Ss * Ss;
    const float scale = 0.3f * conf[b] * (1.0f / 16.0f); // 1/sqrt(256)=1/16

    __shared__ float As[8][128];
    __shared__ float Bs[8][128];
    const int tid = threadIdx.x;
    const int tx = tid & 15, ty = tid >> 4;
    const int m0 = blockIdx.x * 128, n0 = blockIdx.y * 128;
    const int lrow = tid >> 1, lcol = (tid & 1) * 4;

    float acc[8][8];
    #pragma unroll
    for (int i = 0; i < 8; i++)
        #pragma unroll
        for (int j = 0; j < 8; j++) acc[i][j] = 0.f;

    const float* Ap = A  + (size_t)(m0 + lrow) * Ee + lcol;
    const float* Bp = Bm + (size_t)(n0 + lrow) * Ee + lcol;

    for (int kt = 0; kt < Ee; kt += 8) {
        float4 av = *(const float4*)(Ap + kt);
        float4 bv = *(const float4*)(Bp + kt);
        As[lcol + 0][lrow] = av.x; As[lcol + 1][lrow] = av.y;
        As[lcol + 2][lrow] = av.z; As[lcol + 3][lrow] = av.w;
        Bs[lcol + 0][lrow] = bv.x; Bs[lcol + 1][lrow] = bv.y;
        Bs[lcol + 2][lrow] = bv.z; Bs[lcol + 3][lrow] = bv.w;
        __syncthreads();
        #pragma unroll
        for (int k = 0; k < 8; k++) {
            float a[8], bb[8];
            *(float4*)(a)     = *(const float4*)&As[k][ty * 8];
            *(float4*)(a + 4) = *(const float4*)&As[k][ty * 8 + 4];
            *(float4*)(bb)    = *(const float4*)&Bs[k][tx * 8];
            *(float4*)(bb + 4)= *(const float4*)&Bs[k][tx * 8 + 4];
            #pragma unroll
            for (int i = 0; i < 8; i++)
                #pragma unroll
                for (int j = 0; j < 8; j++)
                    acc[i][j] += a[i] * bb[j];
        }
        __syncthreads();
    }

    #pragma unroll
    for (int i = 0; i < 8; i++) {
        const int row = m0 + ty * 8 + i;
        float4 o0, o1;
        o0.x = acc[i][0] * scale; o0.y = acc[i][1] * scale;
        o0.z = acc[i][2] * scale; o0.w = acc[i][3] * scale;
        o1.x = acc[i][4] * scale; o1.y = acc[i][5] * scale;
        o1.z = acc[i][6] * scale; o1.w = acc[i][7] * scale;
        *(float4*)&C[(size_t)row * Ss + n0 + tx * 8]     = o0;
        *(float4*)&C[(size_t)row * Ss + n0 + tx * 8 + 4] = o1;
    }
}

// ---------------- flash attention: per (b, h, 128 q-rows) -------------------
// K-tiles of 64. Online softmax in registers, P staged through SMEM.
#define Q_STRIDE 65
#define SMEM_ATTN ((128*Q_STRIDE + 64*Q_STRIDE + 64*Q_STRIDE + 128*Q_STRIDE) * 4)

__global__ __launch_bounds__(256) void attn_kernel()
{
    extern __shared__ float sm[];
    float* Qs = sm;                          // [128][65] row-major (q, d)
    float* Ks = Qs + 128 * Q_STRIDE;         // [64][65]  (kk, d)
    float* Vs = Ks + 64 * Q_STRIDE;          // [64][65]  (kk, d)
    float* Ps = Vs + 64 * Q_STRIDE;          // [128][65] (q, kk) (64 cols used)

    const int tid = threadIdx.x;
    const int tx = tid & 15, ty = tid >> 4;
    const int q0 = blockIdx.x * 128;
    const int h  = blockIdx.y;
    const int b  = blockIdx.z;

    // load Q tile [128 x 64]
    const float* gq = g_q + ((size_t)(b * Ss + q0)) * Hh + h * HD;
    #pragma unroll
    for (int it = 0; it < 8; it++) {
        int lin = tid + it * 256;           // float4 index over 128x16
        int row = lin >> 4, c4 = (lin & 15) * 4;
        float4 v = *(const float4*)(gq + (size_t)row * Hh + c4);
        float* dst = Qs + row * Q_STRIDE + c4;
        dst[0] = v.x; dst[1] = v.y; dst[2] = v.z; dst[3] = v.w;
    }

    float mrow[8], lrow[8], o[8][4];
    #pragma unroll
    for (int i = 0; i < 8; i++) {
        mrow[i] = -1e30f; lrow[i] = 0.f;
        #pragma unroll
        for (int j = 0; j < 4; j++) o[i][j] = 0.f;
    }

    for (int kt = 0; kt < Ss / 64; kt++) {
        const int k0 = kt * 64;
        // load K and V tiles [64 x 64]
        #pragma unroll
        for (int it = 0; it < 4; it++) {
            int lin = tid + it * 256;
            int row = lin >> 4, c4 = (lin & 15) * 4;
            size_t goff = ((size_t)(b * Ss + k0 + row)) * Hh + h * HD + c4;
            float4 kv = *(const float4*)(g_k + goff);
            float4 vv = *(const float4*)(g_v + goff);
            float* dk = Ks + row * Q_STRIDE + c4;
            float* dv = Vs + row * Q_STRIDE + c4;
            dk[0] = kv.x; dk[1] = kv.y; dk[2] = kv.z; dk[3] = kv.w;
            dv[0] = vv.x; dv[1] = vv.y; dv[2] = vv.z; dv[3] = vv.w;
        }
        __syncthreads();

        // S = Q @ K^T  (128 x 64), thread owns 8 rows x 4 cols
        float s[8][4];
        #pragma unroll
        for (int i = 0; i < 8; i++)
            #pragma unroll
            for (int j = 0; j < 4; j++) s[i][j] = 0.f;

        #pragma unroll 8
        for (int d = 0; d < HD; d++) {
            float a[8];
            #pragma unroll
            for (int i = 0; i < 8; i++) a[i] = Qs[(ty * 8 + i) * Q_STRIDE + d];
            float kk[4];
            #pragma unroll
            for (int j = 0; j < 4; j++) kk[j] = Ks[(tx * 4 + j) * Q_STRIDE + d];
            #pragma unroll
            for (int i = 0; i < 8; i++)
                #pragma unroll
                for (int j = 0; j < 4; j++)
                    s[i][j] += a[i] * kk[j];
        }

        // scale + shared-head experience bias
        const float* bp = g_bias + ((size_t)b * Ss + q0 + ty * 8) * Ss + k0 + tx * 4;
        #pragma unroll
        for (int i = 0; i < 8; i++) {
            float4 bz = *(const float4*)(bp + (size_t)i * Ss);
            s[i][0] = s[i][0] * 0.125f + bz.x;   // 1/sqrt(64)=0.125
            s[i][1] = s[i][1] * 0.125f + bz.y;
            s[i][2] = s[i][2] * 0.125f + bz.z;
            s[i][3] = s[i][3] * 0.125f + bz.w;
        }

        // online softmax update (row stats across the 16 tx lanes = half warp)
        #pragma unroll
        for (int i = 0; i < 8; i++) {
            float rmax = fmaxf(fmaxf(s[i][0], s[i][1]), fmaxf(s[i][2], s[i][3]));
            #pragma unroll
            for (int off = 8; off > 0; off >>= 1)
                rmax = fmaxf(rmax, __shfl_xor_sync(0xffffffffu, rmax, off));
            float nm = fmaxf(mrow[i], rmax);
            float corr = __expf(mrow[i] - nm);
            mrow[i] = nm;
            float rs = 0.f;
            #pragma unroll
            for (int j = 0; j < 4; j++) { s[i][j] = __expf(s[i][j] - nm); rs += s[i][j]; }
            #pragma unroll
            for (int off = 8; off > 0; off >>= 1)
                rs += __shfl_xor_sync(0xffffffffu, rs, off);
            lrow[i] = lrow[i] * corr + rs;
            #pragma unroll
            for (int j = 0; j < 4; j++) o[i][j] *= corr;
            float* pp = Ps + (ty * 8 + i) * Q_STRIDE + tx * 4;
            pp[0] = s[i][0]; pp[1] = s[i][1]; pp[2] = s[i][2]; pp[3] = s[i][3];
        }
        __syncthreads();

        // O += P @ V   (thread owns 8 q-rows x 4 d-cols)
        #pragma unroll 8
        for (int kk2 = 0; kk2 < 64; kk2++) {
            float p[8];
            #pragma unroll
            for (int i = 0; i < 8; i++) p[i] = Ps[(ty * 8 + i) * Q_STRIDE + kk2];
            float vv[4];
            #pragma unroll
            for (int j = 0; j < 4; j++) vv[j] = Vs[kk2 * Q_STRIDE + tx * 4 + j];
            #pragma unroll
            for (int i = 0; i < 8; i++)
                #pragma unroll
                for (int j = 0; j < 4; j++)
                    o[i][j] += p[i] * vv[j];
        }
        __syncthreads();
    }

    // normalize + write ctx
    #pragma unroll
    for (int i = 0; i < 8; i++) {
        float inv = 1.0f / lrow[i];
        float4 ov;
        ov.x = o[i][0] * inv; ov.y = o[i][1] * inv;
        ov.z = o[i][2] * inv; ov.w = o[i][3] * inv;
        *(float4*)&g_ctx[((size_t)(b * Ss + q0 + ty * 8 + i)) * Hh + h * HD + tx * 4] = ov;
    }
}

// ---------------- launch ----------------------------------------------------
extern "C" void kernel_launch(void* const* d_in, const int* in_sizes, int n_in,
                              void* d_out, int out_size)
{
    const float* x    = (const float*)d_in[0];
    const float* conf = (const float*)d_in[1];
    const float* Wq   = (const float*)d_in[2];
    const float* bq   = (const float*)d_in[3];
    const float* Wk   = (const float*)d_in[4];
    const float* bk   = (const float*)d_in[5];
    const float* Wv   = (const float*)d_in[6];
    const float* bv   = (const float*)d_in[7];
    const float* Weq  = (const float*)d_in[8];
    const float* beq  = (const float*)d_in[9];
    const float* Wek  = (const float*)d_in[10];
    const float* bek  = (const float*)d_in[11];
    const float* Wo   = (const float*)d_in[12];
    const float* bo   = (const float*)d_in[13];
    float* out = (float*)d_out;

    float *pq, *pk, *pv, *peq, *pek, *pctx;
    cudaGetSymbolAddress((void**)&pq,   g_q);
    cudaGetSymbolAddress((void**)&pk,   g_k);
    cudaGetSymbolAddress((void**)&pv,   g_v);
    cudaGetSymbolAddress((void**)&peq,  g_eq);
    cudaGetSymbolAddress((void**)&pek,  g_ek);
    cudaGetSymbolAddress((void**)&pctx, g_ctx);

    cudaFuncSetAttribute(attn_kernel, cudaFuncAttributeMaxDynamicSharedMemorySize, SMEM_ATTN);

    dim3 blk(256);
    // projections: q, k, v [8192,1024]; eq, ek [8192,256]
    sgemm_bias<<<dim3(Mm / 128, Hh / 128), blk>>>(x, Wq, bq, pq, Hh, Hh);
    sgemm_bias<<<dim3(Mm / 128, Hh / 128), blk>>>(x, Wk, bk, pk, Hh, Hh);
    sgemm_bias<<<dim3(Mm / 128, Hh / 128), blk>>>(x, Wv, bv, pv, Hh, Hh);
    sgemm_bias<<<dim3(Mm / 128, Ee / 128), blk>>>(x, Weq, beq, peq, Ee, Hh);
    sgemm_bias<<<dim3(Mm / 128, Ee / 128), blk>>>(x, Wek, bek, pek, Ee, Hh);
    // shared experience bias (premultiplied by 0.3*conf/16)
    exp_bias_gemm<<<dim3(Ss / 128, Ss / 128, Bb), blk>>>(conf);
    // attention
    attn_kernel<<<dim3(Ss / 128, NH, Bb), blk, SMEM_ATTN>>>();
    // output projection
    sgemm_bias<<<dim3(Mm / 128, Hh / 128), blk>>>(pctx, Wo, bo, out, Hh, Hh);
}

// round 2
// speedup vs baseline: 2.7789x; 2.7789x over previous
#include <cuda_runtime.h>
#include <math.h>
#include <stdint.h>

#define Bb 4
#define Ss 2048
#define Hh 1024
#define NH 16
#define HD 64
#define Ee 256
#define Mm (Bb*Ss)

// ---------------- static device scratch -------------------------------------
__device__ float g_q[(size_t)Mm*Hh];
__device__ float g_k[(size_t)Mm*Hh];
__device__ float g_v[(size_t)Mm*Hh];
__device__ float g_eq[(size_t)Mm*Ee];
__device__ float g_ek[(size_t)Mm*Ee];
__device__ float g_bias[(size_t)Bb*Ss*Ss];   // 0.3*conf*(eq.ek^T)/16
__device__ float g_ctx[(size_t)Mm*Hh];

// ---------------- helpers ----------------------------------------------------
__device__ __forceinline__ unsigned f2tf(float x) {
    unsigned r; asm("cvt.rna.tf32.f32 %0, %1;" : "=r"(r) : "f"(x)); return r;
}
__device__ __forceinline__ void mma8(float& c0, float& c1, float& c2, float& c3,
                                     unsigned a0, unsigned a1, unsigned a2, unsigned a3,
                                     unsigned b0, unsigned b1) {
    asm volatile("mma.sync.aligned.m16n8k8.row.col.f32.tf32.tf32.f32 "
                 "{%0,%1,%2,%3},{%4,%5,%6,%7},{%8,%9},{%0,%1,%2,%3};"
                 : "+f"(c0), "+f"(c1), "+f"(c2), "+f"(c3)
                 : "r"(a0), "r"(a1), "r"(a2), "r"(a3), "r"(b0), "r"(b1));
}
__device__ __forceinline__ void cp16(uint32_t dst, const float* src) {
    asm volatile("cp.async.ca.shared.global [%0], [%1], 16;" :: "r"(dst), "l"(src));
}
#define CP_COMMIT asm volatile("cp.async.commit_group;")
#define CP_WAIT1  asm volatile("cp.async.wait_group 1;")
#define CP_WAIT0  asm volatile("cp.async.wait_group 0;")

// =============================================================================
// GEMM: C[M,N] = A[M,K] @ W[K,N] + bias[N].  tf32 mma, 128x128x32 tiles.
// 8 warps (2x4). As: [m][k] stride 40. Bs: [k][n] stride 132. 2-stage cp.async.
// =============================================================================
#define GBK 32
#define A_STRIDE 40
#define B_STRIDE 132
#define A_TILE (128*A_STRIDE)
#define B_TILE (GBK*B_STRIDE)
#define G_STAGE (A_TILE + B_TILE)
#define GEMM_SMEM (2*G_STAGE*4)

__global__ __launch_bounds__(256) void gemm_tc(
    const float* __restrict__ A, const float* __restrict__ W,
    const float* __restrict__ bias, float* __restrict__ C, int N, int K)
{
    extern __shared__ float sm[];
    const int tid = threadIdx.x, lane = tid & 31, wid = tid >> 5;
    const int wm = wid >> 2, wn = wid & 3;
    const int r = lane >> 2, c = lane & 3;
    const int m0 = blockIdx.x * 128, n0 = blockIdx.y * 128;
    const uint32_t sbase = (uint32_t)__cvta_generic_to_shared(sm);

    float acc[4][4][4];
    #pragma unroll
    for (int i = 0; i < 4; i++)
        #pragma unroll
        for (int j = 0; j < 4; j++)
            #pragma unroll
            for (int q = 0; q < 4; q++) acc[i][j][q] = 0.f;

    const int niter = K / GBK;

    // prologue: stage 0
    {
        const uint32_t aAddr = sbase;
        const uint32_t bAddr = sbase + A_TILE * 4;
        #pragma unroll
        for (int i = 0; i < 4; i++) {
            int lin = tid + i * 256, row = lin >> 3, c4 = (lin & 7) << 2;
            cp16(aAddr + (uint32_t)(row * A_STRIDE + c4) * 4, A + (size_t)(m0 + row) * K + c4);
        }
        #pragma unroll
        for (int i = 0; i < 4; i++) {
            int lin = tid + i * 256, row = lin >> 5, c4 = (lin & 31) << 2;
            cp16(bAddr + (uint32_t)(row * B_STRIDE + c4) * 4, W + (size_t)row * N + n0 + c4);
        }
        CP_COMMIT;
    }

    for (int it = 0; it < niter; it++) {
        if (it + 1 < niter) {
            const int s = (it + 1) & 1, kt = (it + 1) * GBK;
            const uint32_t aAddr = sbase + (uint32_t)(s * G_STAGE) * 4;
            const uint32_t bAddr = aAddr + A_TILE * 4;
            #pragma unroll
            for (int i = 0; i < 4; i++) {
                int lin = tid + i * 256, row = lin >> 3, c4 = (lin & 7) << 2;
                cp16(aAddr + (uint32_t)(row * A_STRIDE + c4) * 4, A + (size_t)(m0 + row) * K + kt + c4);
            }
            #pragma unroll
            for (int i = 0; i < 4; i++) {
                int lin = tid + i * 256, row = lin >> 5, c4 = (lin & 31) << 2;
                cp16(bAddr + (uint32_t)(row * B_STRIDE + c4) * 4, W + (size_t)(kt + row) * N + n0 + c4);
            }
            CP_COMMIT;
            CP_WAIT1;
        } else {
            CP_WAIT0;
        }
        __syncthreads();

        const float* As  = sm + (it & 1) * G_STAGE;
        const float* Bsm = As + A_TILE;
        #pragma unroll
        for (int ks = 0; ks < 4; ks++) {
            unsigned af[4][4];
            #pragma unroll
            for (int mt = 0; mt < 4; mt++) {
                const float* base = As + (64 * wm + 16 * mt + r) * A_STRIDE + 8 * ks + 2 * c;
                float2 lo = *(const float2*)base;
                float2 hi = *(const float2*)(base + 8 * A_STRIDE);
                af[mt][0] = f2tf(lo.x); af[mt][2] = f2tf(lo.y);
                af[mt][1] = f2tf(hi.x); af[mt][3] = f2tf(hi.y);
            }
            unsigned bf[4][2];
            #pragma unroll
            for (int nt = 0; nt < 4; nt++) {
                int col = 32 * wn + 8 * nt + r;
                bf[nt][0] = f2tf(Bsm[(8 * ks + 2 * c) * B_STRIDE + col]);
                bf[nt][1] = f2tf(Bsm[(8 * ks + 2 * c + 1) * B_STRIDE + col]);
            }
            #pragma unroll
            for (int mt = 0; mt < 4; mt++)
                #pragma unroll
                for (int nt = 0; nt < 4; nt++)
                    mma8(acc[mt][nt][0], acc[mt][nt][1], acc[mt][nt][2], acc[mt][nt][3],
                         af[mt][0], af[mt][1], af[mt][2], af[mt][3], bf[nt][0], bf[nt][1]);
        }
        __syncthreads();
    }

    #pragma unroll
    for (int mt = 0; mt < 4; mt++) {
        const int row = m0 + 64 * wm + 16 * mt + r;
        #pragma unroll
        for (int nt = 0; nt < 4; nt++) {
            const int col = n0 + 32 * wn + 8 * nt + 2 * c;
            float2 bz = *(const float2*)(bias + col);
            float2 o0 = { acc[mt][nt][0] + bz.x, acc[mt][nt][1] + bz.y };
            float2 o1 = { acc[mt][nt][2] + bz.x, acc[mt][nt][3] + bz.y };
            *(float2*)&C[(size_t)row * N + col] = o0;
            *(float2*)&C[(size_t)(row + 8) * N + col] = o1;
        }
    }
}

// =============================================================================
// exp-bias GEMM: g_bias[b,i,j] = scale_b * eq[b,i,:].ek[b,j,:]   (K = 256)
// Both operands K-major rows. As/Bs both [row][k] stride 40.
// =============================================================================
#define EB_TILE (128*A_STRIDE)
#define EB_STAGE (2*EB_TILE)
#define EB_SMEM (2*EB_STAGE*4)

__global__ __launch_bounds__(256) void expbias_tc(const float* __restrict__ conf)
{
    extern __shared__ float sm[];
    const int b = blockIdx.z;
    const float* A  = g_eq + (size_t)b * Ss * Ee;
    const float* Bm = g_ek + (size_t)b * Ss * Ee;
    float* C = g_bias + (size_t)b * Ss * Ss;
    const float scale = 0.3f * __ldg(&conf[b]) * (1.0f / 16.0f);

    const int tid = threadIdx.x, lane = tid & 31, wid = tid >> 5;
    const int wm = wid >> 2, wn = wid & 3;
    const int r = lane >> 2, c = lane & 3;
    const int m0 = blockIdx.x * 128, n0 = blockIdx.y * 128;
    const uint32_t sbase = (uint32_t)__cvta_generic_to_shared(sm);

    float acc[4][4][4];
    #pragma unroll
    for (int i = 0; i < 4; i++)
        #pragma unroll
        for (int j = 0; j < 4; j++)
            #pragma unroll
            for (int q = 0; q < 4; q++) acc[i][j][q] = 0.f;

    const int niter = Ee / GBK;  // 8

    {
        const uint32_t aAddr = sbase;
        const uint32_t bAddr = sbase + EB_TILE * 4;
        #pragma unroll
        for (int i = 0; i < 4; i++) {
            int lin = tid + i * 256, row = lin >> 3, c4 = (lin & 7) << 2;
            cp16(aAddr + (uint32_t)(row * A_STRIDE + c4) * 4, A + (size_t)(m0 + row) * Ee + c4);
            cp16(bAddr + (uint32_t)(row * A_STRIDE + c4) * 4, Bm + (size_t)(n0 + row) * Ee + c4);
        }
        CP_COMMIT;
    }

    for (int it = 0; it < niter; it++) {
        if (it + 1 < niter) {
            const int s = (it + 1) & 1, kt = (it + 1) * GBK;
            const uint32_t aAddr = sbase + (uint32_t)(s * EB_STAGE) * 4;
            const uint32_t bAddr = aAddr + EB_TILE * 4;
            #pragma unroll
            for (int i = 0; i < 4; i++) {
                int lin = tid + i * 256, row = lin >> 3, c4 = (lin & 7) << 2;
                cp16(aAddr + (uint32_t)(row * A_STRIDE + c4) * 4, A + (size_t)(m0 + row) * Ee + kt + c4);
                cp16(bAddr + (uint32_t)(row * A_STRIDE + c4) * 4, Bm + (size_t)(n0 + row) * Ee + kt + c4);
            }
            CP_COMMIT;
            CP_WAIT1;
        } else {
            CP_WAIT0;
        }
        __syncthreads();

        const float* As  = sm + (it & 1) * EB_STAGE;
        const float* Bs  = As + EB_TILE;
        #pragma unroll
        for (int ks = 0; ks < 4; ks++) {
            unsigned af[4][4];
            #pragma unroll
            for (int mt = 0; mt < 4; mt++) {
                const float* base = As + (64 * wm + 16 * mt + r) * A_STRIDE + 8 * ks + 2 * c;
                float2 lo = *(const float2*)base;
                float2 hi = *(const float2*)(base + 8 * A_STRIDE);
                af[mt][0] = f2tf(lo.x); af[mt][2] = f2tf(lo.y);
                af[mt][1] = f2tf(hi.x); af[mt][3] = f2tf(hi.y);
            }
            unsigned bf[4][2];
            #pragma unroll
            for (int nt = 0; nt < 4; nt++) {
                const float* base = Bs + (32 * wn + 8 * nt + r) * A_STRIDE + 8 * ks + 2 * c;
                float2 bb = *(const float2*)base;
                bf[nt][0] = f2tf(bb.x); bf[nt][1] = f2tf(bb.y);
            }
            #pragma unroll
            for (int mt = 0; mt < 4; mt++)
                #pragma unroll
                for (int nt = 0; nt < 4; nt++)
                    mma8(acc[mt][nt][0], acc[mt][nt][1], acc[mt][nt][2], acc[mt][nt][3],
                         af[mt][0], af[mt][1], af[mt][2], af[mt][3], bf[nt][0], bf[nt][1]);
        }
        __syncthreads();
    }

    #pragma unroll
    for (int mt = 0; mt < 4; mt++) {
        const int row = m0 + 64 * wm + 16 * mt + r;
        #pragma unroll
        for (int nt = 0; nt < 4; nt++) {
            const int col = n0 + 32 * wn + 8 * nt + 2 * c;
            float2 o0 = { acc[mt][nt][0] * scale, acc[mt][nt][1] * scale };
            float2 o1 = { acc[mt][nt][2] * scale, acc[mt][nt][3] * scale };
            *(float2*)&C[(size_t)row * Ss + col] = o0;
            *(float2*)&C[(size_t)(row + 8) * Ss + col] = o1;
        }
    }
}

// =============================================================================
// Flash attention (tf32 mma). Block: 128 q-rows x (head, batch). 8 warps,
// each warp owns 16 q-rows x full 128-key tile. Q frags in registers.
// K/V pre-converted to tf32 at STS. S-acc fragments feed PV directly.
// =============================================================================
#define KS_STRIDE 72
#define ATTN_SMEM (2*128*KS_STRIDE*4)

__global__ __launch_bounds__(256) void attn_tc()
{
    extern __shared__ float sm[];
    float* Ks = sm;
    float* Vs = sm + 128 * KS_STRIDE;

    const int tid = threadIdx.x, lane = tid & 31, wid = tid >> 5;
    const int r = lane >> 2, c = lane & 3;
    const int q0 = blockIdx.x * 128, h = blockIdx.y, b = blockIdx.z;

    // stage Q (tf32 bits) into Ks
    const float* gq = g_q + ((size_t)(b * Ss + q0)) * Hh + h * HD;
    #pragma unroll
    for (int i = 0; i < 8; i++) {
        int lin = tid + i * 256, row = lin >> 4, c4 = (lin & 15) << 2;
        float4 v = *(const float4*)(gq + (size_t)row * Hh + c4);
        float4 t;
        t.x = __uint_as_float(f2tf(v.x)); t.y = __uint_as_float(f2tf(v.y));
        t.z = __uint_as_float(f2tf(v.z)); t.w = __uint_as_float(f2tf(v.w));
        *(float4*)&Ks[row * KS_STRIDE + c4] = t;
    }
    __syncthreads();

    unsigned qf[8][4];
    #pragma unroll
    for (int ks = 0; ks < 8; ks++) {
        const float* base = Ks + (16 * wid + r) * KS_STRIDE + 8 * ks + 2 * c;
        float2 lo = *(const float2*)base;
        float2 hi = *(const float2*)(base + 8 * KS_STRIDE);
        qf[ks][0] = __float_as_uint(lo.x); qf[ks][2] = __float_as_uint(lo.y);
        qf[ks][1] = __float_as_uint(hi.x); qf[ks][3] = __float_as_uint(hi.y);
    }
    __syncthreads();

    float oacc[8][4];
    #pragma unroll
    for (int i = 0; i < 8; i++)
        #pragma unroll
        for (int j = 0; j < 4; j++) oacc[i][j] = 0.f;
    float ms0 = -1e30f, ms1 = -1e30f, ls0 = 0.f, ls1 = 0.f;

    for (int kt = 0; kt < Ss / 128; kt++) {
        const int k0 = kt * 128;
        #pragma unroll
        for (int i = 0; i < 8; i++) {
            int lin = tid + i * 256, row = lin >> 4, c4 = (lin & 15) << 2;
            size_t go = ((size_t)(b * Ss + k0 + row)) * Hh + h * HD + c4;
            float4 kv = *(const float4*)(g_k + go);
            float4 vv = *(const float4*)(g_v + go);
            float4 tk, tv;
            tk.x = __uint_as_float(f2tf(kv.x)); tk.y = __uint_as_float(f2tf(kv.y));
            tk.z = __uint_as_float(f2tf(kv.z)); tk.w = __uint_as_float(f2tf(kv.w));
            tv.x = __uint_as_float(f2tf(vv.x)); tv.y = __uint_as_float(f2tf(vv.y));
            tv.z = __uint_as_float(f2tf(vv.z)); tv.w = __uint_as_float(f2tf(vv.w));
            *(float4*)&Ks[row * KS_STRIDE + c4] = tk;
            *(float4*)&Vs[row * KS_STRIDE + c4] = tv;
        }
        __syncthreads();

        // S = Q @ K^T  (16 x 128 per warp)
        float sacc[16][4];
        #pragma unroll
        for (int i = 0; i < 16; i++)
            #pragma unroll
            for (int j = 0; j < 4; j++) sacc[i][j] = 0.f;

        #pragma unroll
        for (int ks = 0; ks < 8; ks++) {
            #pragma unroll
            for (int nt = 0; nt < 16; nt++) {
                const float* base = Ks + (8 * nt + r) * KS_STRIDE + 8 * ks + 2 * c;
                float2 bb = *(const float2*)base;
                mma8(sacc[nt][0], sacc[nt][1], sacc[nt][2], sacc[nt][3],
                     qf[ks][0], qf[ks][1], qf[ks][2], qf[ks][3],
                     __float_as_uint(bb.x), __float_as_uint(bb.y));
            }
        }

        // scale + experience bias + online softmax
        const float* bp0 = g_bias + ((size_t)b * Ss + q0 + 16 * wid + r) * Ss + k0 + 2 * c;
        const float* bp1 = bp0 + (size_t)8 * Ss;
        float mx0 = -1e30f, mx1 = -1e30f;
        #pragma unroll
        for (int nt = 0; nt < 16; nt++) {
            float2 z0 = __ldg((const float2*)(bp0 + 8 * nt));
            float2 z1 = __ldg((const float2*)(bp1 + 8 * nt));
            sacc[nt][0] = sacc[nt][0] * 0.125f + z0.x;
            sacc[nt][1] = sacc[nt][1] * 0.125f + z0.y;
            sacc[nt][2] = sacc[nt][2] * 0.125f + z1.x;
            sacc[nt][3] = sacc[nt][3] * 0.125f + z1.y;
            mx0 = fmaxf(mx0, fmaxf(sacc[nt][0], sacc[nt][1]));
            mx1 = fmaxf(mx1, fmaxf(sacc[nt][2], sacc[nt][3]));
        }
        mx0 = fmaxf(mx0, __shfl_xor_sync(0xffffffffu, mx0, 1));
        mx0 = fmaxf(mx0, __shfl_xor_sync(0xffffffffu, mx0, 2));
        mx1 = fmaxf(mx1, __shfl_xor_sync(0xffffffffu, mx1, 1));
        mx1 = fmaxf(mx1, __shfl_xor_sync(0xffffffffu, mx1, 2));

        float nm0 = fmaxf(ms0, mx0), nm1 = fmaxf(ms1, mx1);
        float corr0 = __expf(ms0 - nm0), corr1 = __expf(ms1 - nm1);
        ms0 = nm0; ms1 = nm1;

        float rs0 = 0.f, rs1 = 0.f;
        #pragma unroll
        for (int nt = 0; nt < 16; nt++) {
            sacc[nt][0] = __expf(sacc[nt][0] - nm0);
            sacc[nt][1] = __expf(sacc[nt][1] - nm0);
            sacc[nt][2] = __expf(sacc[nt][2] - nm1);
            sacc[nt][3] = __expf(sacc[nt][3] - nm1);
            rs0 += sacc[nt][0] + sacc[nt][1];
            rs1 += sacc[nt][2] + sacc[nt][3];
        }
        rs0 += __shfl_xor_sync(0xffffffffu, rs0, 1);
        rs0 += __shfl_xor_sync(0xffffffffu, rs0, 2);
        rs1 += __shfl_xor_sync(0xffffffffu, rs1, 1);
        rs1 += __shfl_xor_sync(0xffffffffu, rs1, 2);
        ls0 = ls0 * corr0 + rs0;
        ls1 = ls1 * corr1 + rs1;

        #pragma unroll
        for (int nt = 0; nt < 8; nt++) {
            oacc[nt][0] *= corr0; oacc[nt][1] *= corr0;
            oacc[nt][2] *= corr1; oacc[nt][3] *= corr1;
        }

        // O += P @ V   (P fragments = S accumulator fragments, k-permuted)
        #pragma unroll
        for (int j = 0; j < 16; j++) {
            unsigned a0 = f2tf(sacc[j][0]), a1 = f2tf(sacc[j][2]);
            unsigned a2 = f2tf(sacc[j][1]), a3 = f2tf(sacc[j][3]);
            #pragma unroll
            for (int nt = 0; nt < 8; nt++) {
                unsigned b0 = __float_as_uint(Vs[(8 * j + 2 * c) * KS_STRIDE + 8 * nt + r]);
                unsigned b1 = __float_as_uint(Vs[(8 * j + 2 * c + 1) * KS_STRIDE + 8 * nt + r]);
                mma8(oacc[nt][0], oacc[nt][1], oacc[nt][2], oacc[nt][3],
                     a0, a1, a2, a3, b0, b1);
            }
        }
        __syncthreads();
    }

    const float inv0 = 1.0f / ls0, inv1 = 1.0f / ls1;
    const int row = q0 + 16 * wid + r;
    #pragma unroll
    for (int nt = 0; nt < 8; nt++) {
        const int col = h * HD + 8 * nt + 2 * c;
        float2 o0 = { oacc[nt][0] * inv0, oacc[nt][1] * inv0 };
        float2 o1 = { oacc[nt][2] * inv1, oacc[nt][3] * inv1 };
        *(float2*)&g_ctx[((size_t)(b * Ss + row)) * Hh + col] = o0;
        *(float2*)&g_ctx[((size_t)(b * Ss + row + 8)) * Hh + col] = o1;
    }
}

// ---------------- launch ------------------------------------------------------
extern "C" void kernel_launch(void* const* d_in, const int* in_sizes, int n_in,
                              void* d_out, int out_size)
{
    const float* x    = (const float*)d_in[0];
    const float* conf = (const float*)d_in[1];
    const float* Wq   = (const float*)d_in[2];
    const float* bq   = (const float*)d_in[3];
    const float* Wk   = (const float*)d_in[4];
    const float* bk   = (const float*)d_in[5];
    const float* Wv   = (const float*)d_in[6];
    const float* bv   = (const float*)d_in[7];
    const float* Weq  = (const float*)d_in[8];
    const float* beq  = (const float*)d_in[9];
    const float* Wek  = (const float*)d_in[10];
    const float* bek  = (const float*)d_in[11];
    const float* Wo   = (const float*)d_in[12];
    const float* bo   = (const float*)d_in[13];
    float* out = (float*)d_out;

    float *pq, *pk, *pv, *peq, *pek, *pctx;
    cudaGetSymbolAddress((void**)&pq,   g_q);
    cudaGetSymbolAddress((void**)&pk,   g_k);
    cudaGetSymbolAddress((void**)&pv,   g_v);
    cudaGetSymbolAddress((void**)&peq,  g_eq);
    cudaGetSymbolAddress((void**)&pek,  g_ek);
    cudaGetSymbolAddress((void**)&pctx, g_ctx);

    cudaFuncSetAttribute(gemm_tc,    cudaFuncAttributeMaxDynamicSharedMemorySize, GEMM_SMEM);
    cudaFuncSetAttribute(expbias_tc, cudaFuncAttributeMaxDynamicSharedMemorySize, EB_SMEM);
    cudaFuncSetAttribute(attn_tc,    cudaFuncAttributeMaxDynamicSharedMemorySize, ATTN_SMEM);

    dim3 blk(256);
    gemm_tc<<<dim3(Mm / 128, Hh / 128), blk, GEMM_SMEM>>>(x, Wq, bq, pq, Hh, Hh);
    gemm_tc<<<dim3(Mm / 128, Hh / 128), blk, GEMM_SMEM>>>(x, Wk, bk, pk, Hh, Hh);
    gemm_tc<<<dim3(Mm / 128, Hh / 128), blk, GEMM_SMEM>>>(x, Wv, bv, pv, Hh, Hh);
    gemm_tc<<<dim3(Mm / 128, Ee / 128), blk, GEMM_SMEM>>>(x, Weq, beq, peq, Ee, Hh);
    gemm_tc<<<dim3(Mm / 128, Ee / 128), blk, GEMM_SMEM>>>(x, Wek, bek, pek, Ee, Hh);
    expbias_tc<<<dim3(Ss / 128, Ss / 128, Bb), blk, EB_SMEM>>>(conf);
    attn_tc<<<dim3(Ss / 128, NH, Bb), blk, ATTN_SMEM>>>();
    gemm_tc<<<dim3(Mm / 128, Hh / 128), blk, GEMM_SMEM>>>(pctx, Wo, bo, out, Hh, Hh);
}

// round 3
// speedup vs baseline: 3.1881x; 1.1473x over previous
#include <cuda_runtime.h>
#include <math.h>
#include <stdint.h>

#define Bb 4
#define Ss 2048
#define Hh 1024
#define NH 16
#define HD 64
#define Ee 256
#define Mm (Bb*Ss)

// ---------------- static device scratch -------------------------------------
__device__ float g_q[(size_t)Mm*Hh];
__device__ float g_k[(size_t)Mm*Hh];
__device__ float g_v[(size_t)Mm*Hh];
__device__ float g_eq[(size_t)Mm*Ee];
__device__ float g_ek[(size_t)Mm*Ee];
__device__ float g_bias[(size_t)Bb*Ss*Ss];
__device__ float g_ctx[(size_t)Mm*Hh];
__device__ float g_xr[(size_t)Mm*Hh];                    // tf32-rounded x
__device__ float g_wr[(size_t)4*Hh*Hh + 2*Hh*Ee];        // tf32-rounded weights (packed)

#define OFF_WQ  ((size_t)0)
#define OFF_WK  ((size_t)1*Hh*Hh)
#define OFF_WV  ((size_t)2*Hh*Hh)
#define OFF_WO  ((size_t)3*Hh*Hh)
#define OFF_WEQ ((size_t)4*Hh*Hh)
#define OFF_WEK ((size_t)4*Hh*Hh + (size_t)Hh*Ee)

// ---------------- helpers ----------------------------------------------------
__device__ __forceinline__ unsigned f2tf(float x) {
    unsigned r; asm("cvt.rna.tf32.f32 %0, %1;" : "=r"(r) : "f"(x)); return r;
}
__device__ __forceinline__ float rtf(float x) { return __uint_as_float(f2tf(x)); }
__device__ __forceinline__ void mma8(float& c0, float& c1, float& c2, float& c3,
                                     unsigned a0, unsigned a1, unsigned a2, unsigned a3,
                                     unsigned b0, unsigned b1) {
    asm volatile("mma.sync.aligned.m16n8k8.row.col.f32.tf32.tf32.f32 "
                 "{%0,%1,%2,%3},{%4,%5,%6,%7},{%8,%9},{%0,%1,%2,%3};"
                 : "+f"(c0), "+f"(c1), "+f"(c2), "+f"(c3)
                 : "r"(a0), "r"(a1), "r"(a2), "r"(a3), "r"(b0), "r"(b1));
}
__device__ __forceinline__ void cp16(uint32_t dst, const float* src) {
    asm volatile("cp.async.ca.shared.global [%0], [%1], 16;" :: "r"(dst), "l"(src));
}
#define CP_COMMIT asm volatile("cp.async.commit_group;")
#define CP_WAIT1  asm volatile("cp.async.wait_group 1;")
#define CP_WAIT0  asm volatile("cp.async.wait_group 0;")

// ---------------- tf32 pre-round pass ----------------------------------------
__global__ __launch_bounds__(256) void round_tf32(const float* __restrict__ in,
                                                  float* __restrict__ out, int n4)
{
    int i = blockIdx.x * 256 + threadIdx.x;
    if (i < n4) {
        float4 v = ((const float4*)in)[i];
        float4 t = { rtf(v.x), rtf(v.y), rtf(v.z), rtf(v.w) };
        ((float4*)out)[i] = t;
    }
}

// =============================================================================
// GEMM: C[M,N] = A[M,K] @ W[K,N] + bias[N].  tf32 mma, 128x128x32 tiles.
// Operands pre-rounded to tf32 bits -> NO cvt in hot loop. 2 CTAs/SM.
// =============================================================================
#define GBK 32
#define A_STRIDE 40
#define B_STRIDE 132
#define A_TILE (128*A_STRIDE)
#define B_TILE (GBK*B_STRIDE)
#define G_STAGE (A_TILE + B_TILE)
#define GEMM_SMEM (2*G_STAGE*4)

__global__ __launch_bounds__(256, 2) void gemm_tc(
    const float* __restrict__ A, const float* __restrict__ W,
    const float* __restrict__ bias, float* __restrict__ C,
    int N, int K, int roundOut)
{
    extern __shared__ float sm[];
    const int tid = threadIdx.x, lane = tid & 31, wid = tid >> 5;
    const int wm = wid >> 2, wn = wid & 3;
    const int r = lane >> 2, c = lane & 3;
    const int m0 = blockIdx.x * 128, n0 = blockIdx.y * 128;
    const uint32_t sbase = (uint32_t)__cvta_generic_to_shared(sm);

    float acc[4][4][4];
    #pragma unroll
    for (int i = 0; i < 4; i++)
        #pragma unroll
        for (int j = 0; j < 4; j++)
            #pragma unroll
            for (int q = 0; q < 4; q++) acc[i][j][q] = 0.f;

    const int niter = K / GBK;

    {
        const uint32_t aAddr = sbase;
        const uint32_t bAddr = sbase + A_TILE * 4;
        #pragma unroll
        for (int i = 0; i < 4; i++) {
            int lin = tid + i * 256, row = lin >> 3, c4 = (lin & 7) << 2;
            cp16(aAddr + (uint32_t)(row * A_STRIDE + c4) * 4, A + (size_t)(m0 + row) * K + c4);
        }
        #pragma unroll
        for (int i = 0; i < 4; i++) {
            int lin = tid + i * 256, row = lin >> 5, c4 = (lin & 31) << 2;
            cp16(bAddr + (uint32_t)(row * B_STRIDE + c4) * 4, W + (size_t)row * N + n0 + c4);
        }
        CP_COMMIT;
    }

    for (int it = 0; it < niter; it++) {
        if (it + 1 < niter) {
            const int s = (it + 1) & 1, kt = (it + 1) * GBK;
            const uint32_t aAddr = sbase + (uint32_t)(s * G_STAGE) * 4;
            const uint32_t bAddr = aAddr + A_TILE * 4;
            #pragma unroll
            for (int i = 0; i < 4; i++) {
                int lin = tid + i * 256, row = lin >> 3, c4 = (lin & 7) << 2;
                cp16(aAddr + (uint32_t)(row * A_STRIDE + c4) * 4, A + (size_t)(m0 + row) * K + kt + c4);
            }
            #pragma unroll
            for (int i = 0; i < 4; i++) {
                int lin = tid + i * 256, row = lin >> 5, c4 = (lin & 31) << 2;
                cp16(bAddr + (uint32_t)(row * B_STRIDE + c4) * 4, W + (size_t)(kt + row) * N + n0 + c4);
            }
            CP_COMMIT;
            CP_WAIT1;
        } else {
            CP_WAIT0;
        }
        __syncthreads();

        const float* As  = sm + (it & 1) * G_STAGE;
        const float* Bsm = As + A_TILE;
        #pragma unroll
        for (int ks = 0; ks < 4; ks++) {
            unsigned af[4][4];
            #pragma unroll
            for (int mt = 0; mt < 4; mt++) {
                const float* base = As + (64 * wm + 16 * mt + r) * A_STRIDE + 8 * ks + 2 * c;
                float2 lo = *(const float2*)base;
                float2 hi = *(const float2*)(base + 8 * A_STRIDE);
                af[mt][0] = __float_as_uint(lo.x); af[mt][2] = __float_as_uint(lo.y);
                af[mt][1] = __float_as_uint(hi.x); af[mt][3] = __float_as_uint(hi.y);
            }
            unsigned bf[4][2];
            #pragma unroll
            for (int nt = 0; nt < 4; nt++) {
                int col = 32 * wn + 8 * nt + r;
                bf[nt][0] = __float_as_uint(Bsm[(8 * ks + 2 * c) * B_STRIDE + col]);
                bf[nt][1] = __float_as_uint(Bsm[(8 * ks + 2 * c + 1) * B_STRIDE + col]);
            }
            #pragma unroll
            for (int mt = 0; mt < 4; mt++)
                #pragma unroll
                for (int nt = 0; nt < 4; nt++)
                    mma8(acc[mt][nt][0], acc[mt][nt][1], acc[mt][nt][2], acc[mt][nt][3],
                         af[mt][0], af[mt][1], af[mt][2], af[mt][3], bf[nt][0], bf[nt][1]);
        }
        __syncthreads();
    }

    #pragma unroll
    for (int mt = 0; mt < 4; mt++) {
        const int row = m0 + 64 * wm + 16 * mt + r;
        #pragma unroll
        for (int nt = 0; nt < 4; nt++) {
            const int col = n0 + 32 * wn + 8 * nt + 2 * c;
            float2 bz = *(const float2*)(bias + col);
            float2 o0 = { acc[mt][nt][0] + bz.x, acc[mt][nt][1] + bz.y };
            float2 o1 = { acc[mt][nt][2] + bz.x, acc[mt][nt][3] + bz.y };
            if (roundOut) {
                o0.x = rtf(o0.x); o0.y = rtf(o0.y);
                o1.x = rtf(o1.x); o1.y = rtf(o1.y);
            }
            *(float2*)&C[(size_t)row * N + col] = o0;
            *(float2*)&C[(size_t)(row + 8) * N + col] = o1;
        }
    }
}

// =============================================================================
// exp-bias GEMM: g_bias[b,i,j] = scale_b * eq[b,i,:].ek[b,j,:]   (K = 256)
// eq/ek already tf32-rounded by projection epilogue. 2 CTAs/SM.
// =============================================================================
#define EB_TILE (128*A_STRIDE)
#define EB_STAGE (2*EB_TILE)
#define EB_SMEM (2*EB_STAGE*4)

__global__ __launch_bounds__(256, 2) void expbias_tc(const float* __restrict__ conf)
{
    extern __shared__ float sm[];
    const int b = blockIdx.z;
    const float* A  = g_eq + (size_t)b * Ss * Ee;
    const float* Bm = g_ek + (size_t)b * Ss * Ee;
    float* C = g_bias + (size_t)b * Ss * Ss;
    const float scale = 0.3f * __ldg(&conf[b]) * (1.0f / 16.0f);

    const int tid = threadIdx.x, lane = tid & 31, wid = tid >> 5;
    const int wm = wid >> 2, wn = wid & 3;
    const int r = lane >> 2, c = lane & 3;
    const int m0 = blockIdx.x * 128, n0 = blockIdx.y * 128;
    const uint32_t sbase = (uint32_t)__cvta_generic_to_shared(sm);

    float acc[4][4][4];
    #pragma unroll
    for (int i = 0; i < 4; i++)
        #pragma unroll
        for (int j = 0; j < 4; j++)
            #pragma unroll
            for (int q = 0; q < 4; q++) acc[i][j][q] = 0.f;

    const int niter = Ee / GBK;

    {
        const uint32_t aAddr = sbase;
        const uint32_t bAddr = sbase + EB_TILE * 4;
        #pragma unroll
        for (int i = 0; i < 4; i++) {
            int lin = tid + i * 256, row = lin >> 3, c4 = (lin & 7) << 2;
            cp16(aAddr + (uint32_t)(row * A_STRIDE + c4) * 4, A + (size_t)(m0 + row) * Ee + c4);
            cp16(bAddr + (uint32_t)(row * A_STRIDE + c4) * 4, Bm + (size_t)(n0 + row) * Ee + c4);
        }
        CP_COMMIT;
    }

    for (int it = 0; it < niter; it++) {
        if (it + 1 < niter) {
            const int s = (it + 1) & 1, kt = (it + 1) * GBK;
            const uint32_t aAddr = sbase + (uint32_t)(s * EB_STAGE) * 4;
            const uint32_t bAddr = aAddr + EB_TILE * 4;
            #pragma unroll
            for (int i = 0; i < 4; i++) {
                int lin = tid + i * 256, row = lin >> 3, c4 = (lin & 7) << 2;
                cp16(aAddr + (uint32_t)(row * A_STRIDE + c4) * 4, A + (size_t)(m0 + row) * Ee + kt + c4);
                cp16(bAddr + (uint32_t)(row * A_STRIDE + c4) * 4, Bm + (size_t)(n0 + row) * Ee + kt + c4);
            }
            CP_COMMIT;
            CP_WAIT1;
        } else {
            CP_WAIT0;
        }
        __syncthreads();

        const float* As  = sm + (it & 1) * EB_STAGE;
        const float* Bs  = As + EB_TILE;
        #pragma unroll
        for (int ks = 0; ks < 4; ks++) {
            unsigned af[4][4];
            #pragma unroll
            for (int mt = 0; mt < 4; mt++) {
                const float* base = As + (64 * wm + 16 * mt + r) * A_STRIDE + 8 * ks + 2 * c;
                float2 lo = *(const float2*)base;
                float2 hi = *(const float2*)(base + 8 * A_STRIDE);
                af[mt][0] = __float_as_uint(lo.x); af[mt][2] = __float_as_uint(lo.y);
                af[mt][1] = __float_as_uint(hi.x); af[mt][3] = __float_as_uint(hi.y);
            }
            unsigned bf[4][2];
            #pragma unroll
            for (int nt = 0; nt < 4; nt++) {
                const float* base = Bs + (32 * wn + 8 * nt + r) * A_STRIDE + 8 * ks + 2 * c;
                float2 bb = *(const float2*)base;
                bf[nt][0] = __float_as_uint(bb.x); bf[nt][1] = __float_as_uint(bb.y);
            }
            #pragma unroll
            for (int mt = 0; mt < 4; mt++)
                #pragma unroll
                for (int nt = 0; nt < 4; nt++)
                    mma8(acc[mt][nt][0], acc[mt][nt][1], acc[mt][nt][2], acc[mt][nt][3],
                         af[mt][0], af[mt][1], af[mt][2], af[mt][3], bf[nt][0], bf[nt][1]);
        }
        __syncthreads();
    }

    #pragma unroll
    for (int mt = 0; mt < 4; mt++) {
        const int row = m0 + 64 * wm + 16 * mt + r;
        #pragma unroll
        for (int nt = 0; nt < 4; nt++) {
            const int col = n0 + 32 * wn + 8 * nt + 2 * c;
            float2 o0 = { acc[mt][nt][0] * scale, acc[mt][nt][1] * scale };
            float2 o1 = { acc[mt][nt][2] * scale, acc[mt][nt][3] * scale };
            *(float2*)&C[(size_t)row * Ss + col] = o0;
            *(float2*)&C[(size_t)(row + 8) * Ss + col] = o1;
        }
    }
}

// =============================================================================
// Flash attention. 128 q-rows per block, 64-key tiles, 8 warps, 2 CTAs/SM.
// Q/K/V pre-rounded tf32 -> no cvt on load. Bias folded into accumulator init.
// =============================================================================
#define KS_STRIDE 72
#define ATTN_SMEM (128*KS_STRIDE*4)

__global__ __launch_bounds__(256, 2) void attn_tc()
{
    extern __shared__ float sm[];
    float* Ks = sm;                       // K tile [64][72]
    float* Vs = sm + 64 * KS_STRIDE;      // V tile [64][72]
    float* Qs = sm;                       // Q staging [128][72] (overlaps K/V, used once)

    const int tid = threadIdx.x, lane = tid & 31, wid = tid >> 5;
    const int r = lane >> 2, c = lane & 3;
    const int q0 = blockIdx.x * 128, h = blockIdx.y, b = blockIdx.z;
    const uint32_t sbase = (uint32_t)__cvta_generic_to_shared(sm);
    const uint32_t ksAddr = sbase;
    const uint32_t vsAddr = sbase + 64 * KS_STRIDE * 4;

    // stage Q tile [128 x 64] via cp.async
    const float* gq = g_q + ((size_t)(b * Ss + q0)) * Hh + h * HD;
    #pragma unroll
    for (int i = 0; i < 8; i++) {
        int lin = tid + i * 256, row = lin >> 4, c4 = (lin & 15) << 2;
        cp16(sbase + (uint32_t)(row * KS_STRIDE + c4) * 4, gq + (size_t)row * Hh + c4);
    }
    CP_COMMIT; CP_WAIT0;
    __syncthreads();

    unsigned qf[8][4];
    #pragma unroll
    for (int ks = 0; ks < 8; ks++) {
        const float* base = Qs + (16 * wid + r) * KS_STRIDE + 8 * ks + 2 * c;
        float2 lo = *(const float2*)base;
        float2 hi = *(const float2*)(base + 8 * KS_STRIDE);
        qf[ks][0] = __float_as_uint(lo.x); qf[ks][2] = __float_as_uint(lo.y);
        qf[ks][1] = __float_as_uint(hi.x); qf[ks][3] = __float_as_uint(hi.y);
    }
    __syncthreads();

    float oacc[8][4];
    #pragma unroll
    for (int i = 0; i < 8; i++)
        #pragma unroll
        for (int j = 0; j < 4; j++) oacc[i][j] = 0.f;
    float ms0 = -1e30f, ms1 = -1e30f, ls0 = 0.f, ls1 = 0.f;

    const float* bias_row0 = g_bias + ((size_t)b * Ss + q0 + 16 * wid + r) * Ss;
    const float* bias_row1 = bias_row0 + (size_t)8 * Ss;

    for (int kt = 0; kt < Ss / 64; kt++) {
        const int k0 = kt * 64;
        // async load K/V tile [64 x 64]
        #pragma unroll
        for (int i = 0; i < 4; i++) {
            int lin = tid + i * 256, row = lin >> 4, c4 = (lin & 15) << 2;
            size_t go = ((size_t)(b * Ss + k0 + row)) * Hh + h * HD + c4;
            cp16(ksAddr + (uint32_t)(row * KS_STRIDE + c4) * 4, g_k + go);
            cp16(vsAddr + (uint32_t)(row * KS_STRIDE + c4) * 4, g_v + go);
        }
        CP_COMMIT;

        // init accumulators with 8x experience bias (LDG overlaps cp.async wait)
        float sacc[8][4];
        #pragma unroll
        for (int nt = 0; nt < 8; nt++) {
            float2 z0 = __ldg((const float2*)(bias_row0 + k0 + 8 * nt + 2 * c));
            float2 z1 = __ldg((const float2*)(bias_row1 + k0 + 8 * nt + 2 * c));
            sacc[nt][0] = 8.f * z0.x; sacc[nt][1] = 8.f * z0.y;
            sacc[nt][2] = 8.f * z1.x; sacc[nt][3] = 8.f * z1.y;
        }
        CP_WAIT0;
        __syncthreads();

        // S = Q @ K^T  (16 x 64 per warp)
        #pragma unroll
        for (int ks = 0; ks < 8; ks++) {
            #pragma unroll
            for (int nt = 0; nt < 8; nt++) {
                const float* base = Ks + (8 * nt + r) * KS_STRIDE + 8 * ks + 2 * c;
                float2 bb = *(const float2*)base;
                mma8(sacc[nt][0], sacc[nt][1], sacc[nt][2], sacc[nt][3],
                     qf[ks][0], qf[ks][1], qf[ks][2], qf[ks][3],
                     __float_as_uint(bb.x), __float_as_uint(bb.y));
            }
        }

        // scale + online softmax
        float mx0 = -1e30f, mx1 = -1e30f;
        #pragma unroll
        for (int nt = 0; nt < 8; nt++) {
            sacc[nt][0] *= 0.125f; sacc[nt][1] *= 0.125f;
            sacc[nt][2] *= 0.125f; sacc[nt][3] *= 0.125f;
            mx0 = fmaxf(mx0, fmaxf(sacc[nt][0], sacc[nt][1]));
            mx1 = fmaxf(mx1, fmaxf(sacc[nt][2], sacc[nt][3]));
        }
        mx0 = fmaxf(mx0, __shfl_xor_sync(0xffffffffu, mx0, 1));
        mx0 = fmaxf(mx0, __shfl_xor_sync(0xffffffffu, mx0, 2));
        mx1 = fmaxf(mx1, __shfl_xor_sync(0xffffffffu, mx1, 1));
        mx1 = fmaxf(mx1, __shfl_xor_sync(0xffffffffu, mx1, 2));

        float nm0 = fmaxf(ms0, mx0), nm1 = fmaxf(ms1, mx1);
        float corr0 = __expf(ms0 - nm0), corr1 = __expf(ms1 - nm1);
        ms0 = nm0; ms1 = nm1;

        float rs0 = 0.f, rs1 = 0.f;
        #pragma unroll
        for (int nt = 0; nt < 8; nt++) {
            sacc[nt][0] = __expf(sacc[nt][0] - nm0);
            sacc[nt][1] = __expf(sacc[nt][1] - nm0);
            sacc[nt][2] = __expf(sacc[nt][2] - nm1);
            sacc[nt][3] = __expf(sacc[nt][3] - nm1);
            rs0 += sacc[nt][0] + sacc[nt][1];
            rs1 += sacc[nt][2] + sacc[nt][3];
        }
        rs0 += __shfl_xor_sync(0xffffffffu, rs0, 1);
        rs0 += __shfl_xor_sync(0xffffffffu, rs0, 2);
        rs1 += __shfl_xor_sync(0xffffffffu, rs1, 1);
        rs1 += __shfl_xor_sync(0xffffffffu, rs1, 2);
        ls0 = ls0 * corr0 + rs0;
        ls1 = ls1 * corr1 + rs1;

        #pragma unroll
        for (int nt = 0; nt < 8; nt++) {
            oacc[nt][0] *= corr0; oacc[nt][1] *= corr0;
            oacc[nt][2] *= corr1; oacc[nt][3] *= corr1;
        }

        // O += P @ V   (P frags from S accumulator, k-permuted)
        #pragma unroll
        for (int j = 0; j < 8; j++) {
            unsigned a0 = f2tf(sacc[j][0]), a1 = f2tf(sacc[j][2]);
            unsigned a2 = f2tf(sacc[j][1]), a3 = f2tf(sacc[j][3]);
            #pragma unroll
            for (int nt = 0; nt < 8; nt++) {
                unsigned b0 = __float_as_uint(Vs[(8 * j + 2 * c) * KS_STRIDE + 8 * nt + r]);
                unsigned b1 = __float_as_uint(Vs[(8 * j + 2 * c + 1) * KS_STRIDE + 8 * nt + r]);
                mma8(oacc[nt][0], oacc[nt][1], oacc[nt][2], oacc[nt][3],
                     a0, a1, a2, a3, b0, b1);
            }
        }
        __syncthreads();
    }

    const float inv0 = 1.0f / ls0, inv1 = 1.0f / ls1;
    const int row = q0 + 16 * wid + r;
    #pragma unroll
    for (int nt = 0; nt < 8; nt++) {
        const int col = h * HD + 8 * nt + 2 * c;
        float2 o0 = { rtf(oacc[nt][0] * inv0), rtf(oacc[nt][1] * inv0) };
        float2 o1 = { rtf(oacc[nt][2] * inv1), rtf(oacc[nt][3] * inv1) };
        *(float2*)&g_ctx[((size_t)(b * Ss + row)) * Hh + col] = o0;
        *(float2*)&g_ctx[((size_t)(b * Ss + row + 8)) * Hh + col] = o1;
    }
}

// ---------------- launch ------------------------------------------------------
extern "C" void kernel_launch(void* const* d_in, const int* in_sizes, int n_in,
                              void* d_out, int out_size)
{
    const float* x    = (const float*)d_in[0];
    const float* conf = (const float*)d_in[1];
    const float* Wq   = (const float*)d_in[2];
    const float* bq   = (const float*)d_in[3];
    const float* Wk   = (const float*)d_in[4];
    const float* bk   = (const float*)d_in[5];
    const float* Wv   = (const float*)d_in[6];
    const float* bv   = (const float*)d_in[7];
    const float* Weq  = (const float*)d_in[8];
    const float* beq  = (const float*)d_in[9];
    const float* Wek  = (const float*)d_in[10];
    const float* bek  = (const float*)d_in[11];
    const float* Wo   = (const float*)d_in[12];
    const float* bo   = (const float*)d_in[13];
    float* out = (float*)d_out;

    float *pq, *pk, *pv, *peq, *pek, *pctx, *pxr, *pwr;
    cudaGetSymbolAddress((void**)&pq,   g_q);
    cudaGetSymbolAddress((void**)&pk,   g_k);
    cudaGetSymbolAddress((void**)&pv,   g_v);
    cudaGetSymbolAddress((void**)&peq,  g_eq);
    cudaGetSymbolAddress((void**)&pek,  g_ek);
    cudaGetSymbolAddress((void**)&pctx, g_ctx);
    cudaGetSymbolAddress((void**)&pxr,  g_xr);
    cudaGetSymbolAddress((void**)&pwr,  g_wr);

    cudaFuncSetAttribute(gemm_tc,    cudaFuncAttributeMaxDynamicSharedMemorySize, GEMM_SMEM);
    cudaFuncSetAttribute(expbias_tc, cudaFuncAttributeMaxDynamicSharedMemorySize, EB_SMEM);
    cudaFuncSetAttribute(attn_tc,    cudaFuncAttributeMaxDynamicSharedMemorySize, ATTN_SMEM);

    dim3 blk(256);

    // pre-round x and weights to tf32 bit patterns
    round_tf32<<<(Mm * Hh / 4 + 255) / 256, blk>>>(x, pxr, Mm * Hh / 4);
    round_tf32<<<(Hh * Hh / 4 + 255) / 256, blk>>>(Wq,  pwr + OFF_WQ,  Hh * Hh / 4);
    round_tf32<<<(Hh * Hh / 4 + 255) / 256, blk>>>(Wk,  pwr + OFF_WK,  Hh * Hh / 4);
    round_tf32<<<(Hh * Hh / 4 + 255) / 256, blk>>>(Wv,  pwr + OFF_WV,  Hh * Hh / 4);
    round_tf32<<<(Hh * Hh / 4 + 255) / 256, blk>>>(Wo,  pwr + OFF_WO,  Hh * Hh / 4);
    round_tf32<<<(Hh * Ee / 4 + 255) / 256, blk>>>(Weq, pwr + OFF_WEQ, Hh * Ee / 4);
    round_tf32<<<(Hh * Ee / 4 + 255) / 256, blk>>>(Wek, pwr + OFF_WEK, Hh * Ee / 4);

    // projections (outputs tf32-rounded for downstream mma consumption)
    gemm_tc<<<dim3(Mm / 128, Hh / 128), blk, GEMM_SMEM>>>(pxr, pwr + OFF_WQ,  bq,  pq,  Hh, Hh, 1);
    gemm_tc<<<dim3(Mm / 128, Hh / 128), blk, GEMM_SMEM>>>(pxr, pwr + OFF_WK,  bk,  pk,  Hh, Hh, 1);
    gemm_tc<<<dim3(Mm / 128, Hh / 128), blk, GEMM_SMEM>>>(pxr, pwr + OFF_WV,  bv,  pv,  Hh, Hh, 1);
    gemm_tc<<<dim3(Mm / 128, Ee / 128), blk, GEMM_SMEM>>>(pxr, pwr + OFF_WEQ, beq, peq, Ee, Hh, 1);
    gemm_tc<<<dim3(Mm / 128, Ee / 128), blk, GEMM_SMEM>>>(pxr, pwr + OFF_WEK, bek, pek, Ee, Hh, 1);
    // shared experience bias
    expbias_tc<<<dim3(Ss / 128, Ss / 128, Bb), blk, EB_SMEM>>>(conf);
    // attention
    attn_tc<<<dim3(Ss / 128, NH, Bb), blk, ATTN_SMEM>>>();
    // output projection (fp32 out, no rounding)
    gemm_tc<<<dim3(Mm / 128, Hh / 128), blk, GEMM_SMEM>>>(pctx, pwr + OFF_WO, bo, out, Hh, Hh, 0);
}

// round 4
// speedup vs baseline: 3.6364x; 1.1406x over previous
#include <cuda_runtime.h>
#include <math.h>
#include <stdint.h>

#define Bb 4
#define Ss 2048
#define Hh 1024
#define NH 16
#define HD 64
#define Ee 256
#define Mm (Bb*Ss)

// ---------------- static device scratch -------------------------------------
__device__ float g_q[(size_t)Mm*Hh];
__device__ float g_k[(size_t)Mm*Hh];
__device__ float g_v[(size_t)Mm*Hh];
__device__ float g_eq[(size_t)Mm*Ee];
__device__ float g_ek[(size_t)Mm*Ee];
__device__ float g_bias[(size_t)Bb*Ss*Ss];
__device__ float g_ctx[(size_t)Mm*Hh];
__device__ float g_xr[(size_t)Mm*Hh];
__device__ float g_wr[(size_t)4*Hh*Hh + 2*Hh*Ee];

#define OFF_WQ  ((size_t)0)
#define OFF_WK  ((size_t)1*Hh*Hh)
#define OFF_WV  ((size_t)2*Hh*Hh)
#define OFF_WO  ((size_t)3*Hh*Hh)
#define OFF_WEQ ((size_t)4*Hh*Hh)
#define OFF_WEK ((size_t)4*Hh*Hh + (size_t)Hh*Ee)

// ---------------- helpers ----------------------------------------------------
__device__ __forceinline__ unsigned f2tf(float x) {
    unsigned r; asm("cvt.rna.tf32.f32 %0, %1;" : "=r"(r) : "f"(x)); return r;
}
__device__ __forceinline__ float rtf(float x) { return __uint_as_float(f2tf(x)); }
__device__ __forceinline__ void mma8(float& c0, float& c1, float& c2, float& c3,
                                     unsigned a0, unsigned a1, unsigned a2, unsigned a3,
                                     unsigned b0, unsigned b1) {
    asm volatile("mma.sync.aligned.m16n8k8.row.col.f32.tf32.tf32.f32 "
                 "{%0,%1,%2,%3},{%4,%5,%6,%7},{%8,%9},{%0,%1,%2,%3};"
                 : "+f"(c0), "+f"(c1), "+f"(c2), "+f"(c3)
                 : "r"(a0), "r"(a1), "r"(a2), "r"(a3), "r"(b0), "r"(b1));
}
__device__ __forceinline__ void cp16(uint32_t dst, const float* src) {
    asm volatile("cp.async.ca.shared.global [%0], [%1], 16;" :: "r"(dst), "l"(src));
}
#define CP_COMMIT asm volatile("cp.async.commit_group;")
#define CP_WAIT1  asm volatile("cp.async.wait_group 1;")
#define CP_WAIT0  asm volatile("cp.async.wait_group 0;")

// ---------------- tf32 pre-round pass ----------------------------------------
__global__ __launch_bounds__(256) void round_tf32(const float* __restrict__ in,
                                                  float* __restrict__ out, int n4)
{
    int i = blockIdx.x * 256 + threadIdx.x;
    if (i < n4) {
        float4 v = ((const float4*)in)[i];
        float4 t = { rtf(v.x), rtf(v.y), rtf(v.z), rtf(v.w) };
        ((float4*)out)[i] = t;
    }
}

// =============================================================================
// GEMM core (device inline): C[M,N] = A[M,K] @ W[K,N] + bias[N]
// =============================================================================
#define GBK 32
#define A_STRIDE 40
#define B_STRIDE 132
#define A_TILE (128*A_STRIDE)
#define B_TILE (GBK*B_STRIDE)
#define G_STAGE (A_TILE + B_TILE)
#define GEMM_SMEM (2*G_STAGE*4)

__device__ __forceinline__ void gemm_body(
    const float* __restrict__ A, const float* __restrict__ W,
    const float* __restrict__ bias, float* __restrict__ C,
    int N, int K, int roundOut, float* sm)
{
    const int tid = threadIdx.x, lane = tid & 31, wid = tid >> 5;
    const int wm = wid >> 2, wn = wid & 3;
    const int r = lane >> 2, c = lane & 3;
    const int m0 = blockIdx.x * 128, n0 = blockIdx.y * 128;
    const uint32_t sbase = (uint32_t)__cvta_generic_to_shared(sm);

    float acc[4][4][4];
    #pragma unroll
    for (int i = 0; i < 4; i++)
        #pragma unroll
        for (int j = 0; j < 4; j++)
            #pragma unroll
            for (int q = 0; q < 4; q++) acc[i][j][q] = 0.f;

    const int niter = K / GBK;
    {
        const uint32_t aAddr = sbase;
        const uint32_t bAddr = sbase + A_TILE * 4;
        #pragma unroll
        for (int i = 0; i < 4; i++) {
            int lin = tid + i * 256, row = lin >> 3, c4 = (lin & 7) << 2;
            cp16(aAddr + (uint32_t)(row * A_STRIDE + c4) * 4, A + (size_t)(m0 + row) * K + c4);
        }
        #pragma unroll
        for (int i = 0; i < 4; i++) {
            int lin = tid + i * 256, row = lin >> 5, c4 = (lin & 31) << 2;
            cp16(bAddr + (uint32_t)(row * B_STRIDE + c4) * 4, W + (size_t)row * N + n0 + c4);
        }
        CP_COMMIT;
    }

    for (int it = 0; it < niter; it++) {
        if (it + 1 < niter) {
            const int s = (it + 1) & 1, kt = (it + 1) * GBK;
            const uint32_t aAddr = sbase + (uint32_t)(s * G_STAGE) * 4;
            const uint32_t bAddr = aAddr + A_TILE * 4;
            #pragma unroll
            for (int i = 0; i < 4; i++) {
                int lin = tid + i * 256, row = lin >> 3, c4 = (lin & 7) << 2;
                cp16(aAddr + (uint32_t)(row * A_STRIDE + c4) * 4, A + (size_t)(m0 + row) * K + kt + c4);
            }
            #pragma unroll
            for (int i = 0; i < 4; i++) {
                int lin = tid + i * 256, row = lin >> 5, c4 = (lin & 31) << 2;
                cp16(bAddr + (uint32_t)(row * B_STRIDE + c4) * 4, W + (size_t)(kt + row) * N + n0 + c4);
            }
            CP_COMMIT;
            CP_WAIT1;
        } else {
            CP_WAIT0;
        }
        __syncthreads();

        const float* As  = sm + (it & 1) * G_STAGE;
        const float* Bsm = As + A_TILE;
        #pragma unroll
        for (int ks = 0; ks < 4; ks++) {
            unsigned af[4][4];
            #pragma unroll
            for (int mt = 0; mt < 4; mt++) {
                const float* base = As + (64 * wm + 16 * mt + r) * A_STRIDE + 8 * ks + 2 * c;
                float2 lo = *(const float2*)base;
                float2 hi = *(const float2*)(base + 8 * A_STRIDE);
                af[mt][0] = __float_as_uint(lo.x); af[mt][2] = __float_as_uint(lo.y);
                af[mt][1] = __float_as_uint(hi.x); af[mt][3] = __float_as_uint(hi.y);
            }
            unsigned bf[4][2];
            #pragma unroll
            for (int nt = 0; nt < 4; nt++) {
                int col = 32 * wn + 8 * nt + r;
                bf[nt][0] = __float_as_uint(Bsm[(8 * ks + 2 * c) * B_STRIDE + col]);
                bf[nt][1] = __float_as_uint(Bsm[(8 * ks + 2 * c + 1) * B_STRIDE + col]);
            }
            #pragma unroll
            for (int mt = 0; mt < 4; mt++)
                #pragma unroll
                for (int nt = 0; nt < 4; nt++)
                    mma8(acc[mt][nt][0], acc[mt][nt][1], acc[mt][nt][2], acc[mt][nt][3],
                         af[mt][0], af[mt][1], af[mt][2], af[mt][3], bf[nt][0], bf[nt][1]);
        }
        __syncthreads();
    }

    #pragma unroll
    for (int mt = 0; mt < 4; mt++) {
        const int row = m0 + 64 * wm + 16 * mt + r;
        #pragma unroll
        for (int nt = 0; nt < 4; nt++) {
            const int col = n0 + 32 * wn + 8 * nt + 2 * c;
            float2 bz = *(const float2*)(bias + col);
            float2 o0 = { acc[mt][nt][0] + bz.x, acc[mt][nt][1] + bz.y };
            float2 o1 = { acc[mt][nt][2] + bz.x, acc[mt][nt][3] + bz.y };
            if (roundOut) {
                o0.x = rtf(o0.x); o0.y = rtf(o0.y);
                o1.x = rtf(o1.x); o1.y = rtf(o1.y);
            }
            *(float2*)&C[(size_t)row * N + col] = o0;
            *(float2*)&C[(size_t)(row + 8) * N + col] = o1;
        }
    }
}

// merged QKV projection (grid.z selects target)
__global__ __launch_bounds__(256, 2) void gemm_qkv(
    const float* __restrict__ A,
    const float* __restrict__ b0v, const float* __restrict__ b1v, const float* __restrict__ b2v)
{
    extern __shared__ float sm[];
    const int z = blockIdx.z;
    const float* W = g_wr + (z == 0 ? OFF_WQ : (z == 1 ? OFF_WK : OFF_WV));
    const float* bias = z == 0 ? b0v : (z == 1 ? b1v : b2v);
    float* C = z == 0 ? g_q : (z == 1 ? g_k : g_v);
    gemm_body(A, W, bias, C, Hh, Hh, 1, sm);
}

// merged eq/ek projection
__global__ __launch_bounds__(256, 2) void gemm_eqk(
    const float* __restrict__ A,
    const float* __restrict__ b0v, const float* __restrict__ b1v)
{
    extern __shared__ float sm[];
    const int z = blockIdx.z;
    const float* W = g_wr + (z == 0 ? OFF_WEQ : OFF_WEK);
    const float* bias = z == 0 ? b0v : b1v;
    float* C = z == 0 ? g_eq : g_ek;
    gemm_body(A, W, bias, C, Ee, Hh, 1, sm);
}

// output projection
__global__ __launch_bounds__(256, 2) void gemm_out(
    const float* __restrict__ A, const float* __restrict__ bias, float* __restrict__ C)
{
    extern __shared__ float sm[];
    gemm_body(A, g_wr + OFF_WO, bias, C, Hh, Hh, 0, sm);
}

// =============================================================================
// exp-bias GEMM: g_bias[b,i,j] = scale_b * eq[b,i,:].ek[b,j,:]   (K = 256)
// =============================================================================
#define EB_TILE (128*A_STRIDE)
#define EB_STAGE (2*EB_TILE)
#define EB_SMEM (2*EB_STAGE*4)

__global__ __launch_bounds__(256, 2) void expbias_tc(const float* __restrict__ conf)
{
    extern __shared__ float sm[];
    const int b = blockIdx.z;
    const float* A  = g_eq + (size_t)b * Ss * Ee;
    const float* Bm = g_ek + (size_t)b * Ss * Ee;
    float* C = g_bias + (size_t)b * Ss * Ss;
    const float scale = 0.3f * __ldg(&conf[b]) * (1.0f / 16.0f);

    const int tid = threadIdx.x, lane = tid & 31, wid = tid >> 5;
    const int wm = wid >> 2, wn = wid & 3;
    const int r = lane >> 2, c = lane & 3;
    const int m0 = blockIdx.x * 128, n0 = blockIdx.y * 128;
    const uint32_t sbase = (uint32_t)__cvta_generic_to_shared(sm);

    float acc[4][4][4];
    #pragma unroll
    for (int i = 0; i < 4; i++)
        #pragma unroll
        for (int j = 0; j < 4; j++)
            #pragma unroll
            for (int q = 0; q < 4; q++) acc[i][j][q] = 0.f;

    const int niter = Ee / GBK;
    {
        const uint32_t aAddr = sbase;
        const uint32_t bAddr = sbase + EB_TILE * 4;
        #pragma unroll
        for (int i = 0; i < 4; i++) {
            int lin = tid + i * 256, row = lin >> 3, c4 = (lin & 7) << 2;
            cp16(aAddr + (uint32_t)(row * A_STRIDE + c4) * 4, A + (size_t)(m0 + row) * Ee + c4);
            cp16(bAddr + (uint32_t)(row * A_STRIDE + c4) * 4, Bm + (size_t)(n0 + row) * Ee + c4);
        }
        CP_COMMIT;
    }

    for (int it = 0; it < niter; it++) {
        if (it + 1 < niter) {
            const int s = (it + 1) & 1, kt = (it + 1) * GBK;
            const uint32_t aAddr = sbase + (uint32_t)(s * EB_STAGE) * 4;
            const uint32_t bAddr = aAddr + EB_TILE * 4;
            #pragma unroll
            for (int i = 0; i < 4; i++) {
                int lin = tid + i * 256, row = lin >> 3, c4 = (lin & 7) << 2;
                cp16(aAddr + (uint32_t)(row * A_STRIDE + c4) * 4, A + (size_t)(m0 + row) * Ee + kt + c4);
                cp16(bAddr + (uint32_t)(row * A_STRIDE + c4) * 4, Bm + (size_t)(n0 + row) * Ee + kt + c4);
            }
            CP_COMMIT;
            CP_WAIT1;
        } else {
            CP_WAIT0;
        }
        __syncthreads();

        const float* As = sm + (it & 1) * EB_STAGE;
        const float* Bs = As + EB_TILE;
        #pragma unroll
        for (int ks = 0; ks < 4; ks++) {
            unsigned af[4][4];
            #pragma unroll
            for (int mt = 0; mt < 4; mt++) {
                const float* base = As + (64 * wm + 16 * mt + r) * A_STRIDE + 8 * ks + 2 * c;
                float2 lo = *(const float2*)base;
                float2 hi = *(const float2*)(base + 8 * A_STRIDE);
                af[mt][0] = __float_as_uint(lo.x); af[mt][2] = __float_as_uint(lo.y);
                af[mt][1] = __float_as_uint(hi.x); af[mt][3] = __float_as_uint(hi.y);
            }
            unsigned bf[4][2];
            #pragma unroll
            for (int nt = 0; nt < 4; nt++) {
                const float* base = Bs + (32 * wn + 8 * nt + r) * A_STRIDE + 8 * ks + 2 * c;
                float2 bb = *(const float2*)base;
                bf[nt][0] = __float_as_uint(bb.x); bf[nt][1] = __float_as_uint(bb.y);
            }
            #pragma unroll
            for (int mt = 0; mt < 4; mt++)
                #pragma unroll
                for (int nt = 0; nt < 4; nt++)
                    mma8(acc[mt][nt][0], acc[mt][nt][1], acc[mt][nt][2], acc[mt][nt][3],
                         af[mt][0], af[mt][1], af[mt][2], af[mt][3], bf[nt][0], bf[nt][1]);
        }
        __syncthreads();
    }

    #pragma unroll
    for (int mt = 0; mt < 4; mt++) {
        const int row = m0 + 64 * wm + 16 * mt + r;
        #pragma unroll
        for (int nt = 0; nt < 4; nt++) {
            const int col = n0 + 32 * wn + 8 * nt + 2 * c;
            float2 o0 = { acc[mt][nt][0] * scale, acc[mt][nt][1] * scale };
            float2 o1 = { acc[mt][nt][2] * scale, acc[mt][nt][3] * scale };
            *(float2*)&C[(size_t)row * Ss + col] = o0;
            *(float2*)&C[(size_t)(row + 8) * Ss + col] = o1;
        }
    }
}

// =============================================================================
// Flash attention, fully pipelined: K/V/bias all cp.async double-buffered.
// 128 q-rows per block, 64-key tiles, 8 warps, 1 CTA/SM (146KB smem).
// =============================================================================
#define KS 72
#define VS 76
#define BSs 72
#define K_OFF 0
#define V_OFF (64*KS)
#define B_OFF (64*KS + 64*VS)
#define STAGE_F (64*KS + 64*VS + 128*BSs)   // 18688 floats
#define ATTN_SMEM (2*STAGE_F*4)              // 149504 bytes

__global__ __launch_bounds__(256, 1) void attn_tc()
{
    extern __shared__ float sm[];
    const int tid = threadIdx.x, lane = tid & 31, wid = tid >> 5;
    const int r = lane >> 2, c = lane & 3;
    const int q0 = blockIdx.x * 128, h = blockIdx.y, b = blockIdx.z;
    const uint32_t sbase = (uint32_t)__cvta_generic_to_shared(sm);

    // ---- stage Q [128x64] (temporarily in stage-0 area, stride KS) ----
    const float* gq = g_q + ((size_t)(b * Ss + q0)) * Hh + h * HD;
    #pragma unroll
    for (int i = 0; i < 8; i++) {
        int lin = tid + i * 256, row = lin >> 4, c4 = (lin & 15) << 2;
        cp16(sbase + (uint32_t)(row * KS + c4) * 4, gq + (size_t)row * Hh + c4);
    }
    CP_COMMIT; CP_WAIT0;
    __syncthreads();

    unsigned qf[8][4];
    #pragma unroll
    for (int ks = 0; ks < 8; ks++) {
        const float* base = sm + (16 * wid + r) * KS + 8 * ks + 2 * c;
        float2 lo = *(const float2*)base;
        float2 hi = *(const float2*)(base + 8 * KS);
        qf[ks][0] = __float_as_uint(lo.x); qf[ks][2] = __float_as_uint(lo.y);
        qf[ks][1] = __float_as_uint(hi.x); qf[ks][3] = __float_as_uint(hi.y);
    }
    __syncthreads();   // all warps done reading Q before stage 0 is overwritten

    const float* bias_base = g_bias + ((size_t)b * Ss + q0) * Ss;
    const size_t kv_base = (size_t)(b * Ss) * Hh + h * HD;

    // ---- prefetch tile 0 ----
    {
        const uint32_t st = sbase;
        #pragma unroll
        for (int i = 0; i < 4; i++) {
            int lin = tid + i * 256, row = lin >> 4, c4 = (lin & 15) << 2;
            size_t go = kv_base + (size_t)row * Hh + c4;
            cp16(st + (uint32_t)(K_OFF + row * KS + c4) * 4, g_k + go);
            cp16(st + (uint32_t)(V_OFF + row * VS + c4) * 4, g_v + go);
        }
        #pragma unroll
        for (int i = 0; i < 8; i++) {
            int lin = tid + i * 256, row = lin >> 4, c4 = (lin & 15) << 2;
            cp16(st + (uint32_t)(B_OFF + row * BSs + c4) * 4, bias_base + (size_t)row * Ss + c4);
        }
        CP_COMMIT;
    }

    float oacc[8][4];
    #pragma unroll
    for (int i = 0; i < 8; i++)
        #pragma unroll
        for (int j = 0; j < 4; j++) oacc[i][j] = 0.f;
    float ms0 = -1e30f, ms1 = -1e30f, ls0 = 0.f, ls1 = 0.f;

    const int NT = Ss / 64;
    for (int kt = 0; kt < NT; kt++) {
        CP_WAIT0;
        __syncthreads();

        // prefetch tile kt+1 into other stage
        if (kt + 1 < NT) {
            const int k1 = (kt + 1) * 64;
            const uint32_t st = sbase + (uint32_t)(((kt + 1) & 1) * STAGE_F) * 4;
            #pragma unroll
            for (int i = 0; i < 4; i++) {
                int lin = tid + i * 256, row = lin >> 4, c4 = (lin & 15) << 2;
                size_t go = kv_base + (size_t)(k1 + row) * Hh + c4;
                cp16(st + (uint32_t)(K_OFF + row * KS + c4) * 4, g_k + go);
                cp16(st + (uint32_t)(V_OFF + row * VS + c4) * 4, g_v + go);
            }
            #pragma unroll
            for (int i = 0; i < 8; i++) {
                int lin = tid + i * 256, row = lin >> 4, c4 = (lin & 15) << 2;
                cp16(st + (uint32_t)(B_OFF + row * BSs + c4) * 4,
                     bias_base + (size_t)row * Ss + k1 + c4);
            }
            CP_COMMIT;
        }

        const float* stage = sm + (kt & 1) * STAGE_F;
        const float* Ks_ = stage + K_OFF;
        const float* Vs_ = stage + V_OFF;
        const float* Bs_ = stage + B_OFF;

        // init sacc = 8 * bias (from smem)
        float sacc[8][4];
        #pragma unroll
        for (int nt = 0; nt < 8; nt++) {
            float2 z0 = *(const float2*)&Bs_[(16 * wid + r) * BSs + 8 * nt + 2 * c];
            float2 z1 = *(const float2*)&Bs_[(16 * wid + r + 8) * BSs + 8 * nt + 2 * c];
            sacc[nt][0] = 8.f * z0.x; sacc[nt][1] = 8.f * z0.y;
            sacc[nt][2] = 8.f * z1.x; sacc[nt][3] = 8.f * z1.y;
        }

        // S = Q @ K^T
        #pragma unroll
        for (int ks = 0; ks < 8; ks++) {
            #pragma unroll
            for (int nt = 0; nt < 8; nt++) {
                const float* base = Ks_ + (8 * nt + r) * KS + 8 * ks + 2 * c;
                float2 bb = *(const float2*)base;
                mma8(sacc[nt][0], sacc[nt][1], sacc[nt][2], sacc[nt][3],
                     qf[ks][0], qf[ks][1], qf[ks][2], qf[ks][3],
                     __float_as_uint(bb.x), __float_as_uint(bb.y));
            }
        }

        // scale + online softmax
        float mx0 = -1e30f, mx1 = -1e30f;
        #pragma unroll
        for (int nt = 0; nt < 8; nt++) {
            sacc[nt][0] *= 0.125f; sacc[nt][1] *= 0.125f;
            sacc[nt][2] *= 0.125f; sacc[nt][3] *= 0.125f;
            mx0 = fmaxf(mx0, fmaxf(sacc[nt][0], sacc[nt][1]));
            mx1 = fmaxf(mx1, fmaxf(sacc[nt][2], sacc[nt][3]));
        }
        mx0 = fmaxf(mx0, __shfl_xor_sync(0xffffffffu, mx0, 1));
        mx0 = fmaxf(mx0, __shfl_xor_sync(0xffffffffu, mx0, 2));
        mx1 = fmaxf(mx1, __shfl_xor_sync(0xffffffffu, mx1, 1));
        mx1 = fmaxf(mx1, __shfl_xor_sync(0xffffffffu, mx1, 2));

        float nm0 = fmaxf(ms0, mx0), nm1 = fmaxf(ms1, mx1);
        float corr0 = __expf(ms0 - nm0), corr1 = __expf(ms1 - nm1);
        ms0 = nm0; ms1 = nm1;

        float rs0 = 0.f, rs1 = 0.f;
        #pragma unroll
        for (int nt = 0; nt < 8; nt++) {
            sacc[nt][0] = __expf(sacc[nt][0] - nm0);
            sacc[nt][1] = __expf(sacc[nt][1] - nm0);
            sacc[nt][2] = __expf(sacc[nt][2] - nm1);
            sacc[nt][3] = __expf(sacc[nt][3] - nm1);
            rs0 += sacc[nt][0] + sacc[nt][1];
            rs1 += sacc[nt][2] + sacc[nt][3];
        }
        rs0 += __shfl_xor_sync(0xffffffffu, rs0, 1);
        rs0 += __shfl_xor_sync(0xffffffffu, rs0, 2);
        rs1 += __shfl_xor_sync(0xffffffffu, rs1, 1);
        rs1 += __shfl_xor_sync(0xffffffffu, rs1, 2);
        ls0 = ls0 * corr0 + rs0;
        ls1 = ls1 * corr1 + rs1;

        #pragma unroll
        for (int nt = 0; nt < 8; nt++) {
            oacc[nt][0] *= corr0; oacc[nt][1] *= corr0;
            oacc[nt][2] *= corr1; oacc[nt][3] *= corr1;
        }

        // O += P @ V  (P frags from S accumulator, k-permuted)
        #pragma unroll
        for (int j = 0; j < 8; j++) {
            unsigned a0 = f2tf(sacc[j][0]), a1 = f2tf(sacc[j][2]);
            unsigned a2 = f2tf(sacc[j][1]), a3 = f2tf(sacc[j][3]);
            #pragma unroll
            for (int nt = 0; nt < 8; nt++) {
                unsigned b0 = __float_as_uint(Vs_[(8 * j + 2 * c) * VS + 8 * nt + r]);
                unsigned b1 = __float_as_uint(Vs_[(8 * j + 2 * c + 1) * VS + 8 * nt + r]);
                mma8(oacc[nt][0], oacc[nt][1], oacc[nt][2], oacc[nt][3],
                     a0, a1, a2, a3, b0, b1);
            }
        }
    }

    const float inv0 = 1.0f / ls0, inv1 = 1.0f / ls1;
    const int row = q0 + 16 * wid + r;
    #pragma unroll
    for (int nt = 0; nt < 8; nt++) {
        const int col = h * HD + 8 * nt + 2 * c;
        float2 o0 = { rtf(oacc[nt][0] * inv0), rtf(oacc[nt][1] * inv0) };
        float2 o1 = { rtf(oacc[nt][2] * inv1), rtf(oacc[nt][3] * inv1) };
        *(float2*)&g_ctx[((size_t)(b * Ss + row)) * Hh + col] = o0;
        *(float2*)&g_ctx[((size_t)(b * Ss + row + 8)) * Hh + col] = o1;
    }
}

// ---------------- launch ------------------------------------------------------
extern "C" void kernel_launch(void* const* d_in, const int* in_sizes, int n_in,
                              void* d_out, int out_size)
{
    const float* x    = (const float*)d_in[0];
    const float* conf = (const float*)d_in[1];
    const float* Wq   = (const float*)d_in[2];
    const float* bq   = (const float*)d_in[3];
    const float* Wk   = (const float*)d_in[4];
    const float* bk   = (const float*)d_in[5];
    const float* Wv   = (const float*)d_in[6];
    const float* bv   = (const float*)d_in[7];
    const float* Weq  = (const float*)d_in[8];
    const float* beq  = (const float*)d_in[9];
    const float* Wek  = (const float*)d_in[10];
    const float* bek  = (const float*)d_in[11];
    const float* Wo   = (const float*)d_in[12];
    const float* bo   = (const float*)d_in[13];
    float* out = (float*)d_out;

    float *pctx, *pxr, *pwr;
    cudaGetSymbolAddress((void**)&pctx, g_ctx);
    cudaGetSymbolAddress((void**)&pxr,  g_xr);
    cudaGetSymbolAddress((void**)&pwr,  g_wr);

    cudaFuncSetAttribute(gemm_qkv,   cudaFuncAttributeMaxDynamicSharedMemorySize, GEMM_SMEM);
    cudaFuncSetAttribute(gemm_eqk,   cudaFuncAttributeMaxDynamicSharedMemorySize, GEMM_SMEM);
    cudaFuncSetAttribute(gemm_out,   cudaFuncAttributeMaxDynamicSharedMemorySize, GEMM_SMEM);
    cudaFuncSetAttribute(expbias_tc, cudaFuncAttributeMaxDynamicSharedMemorySize, EB_SMEM);
    cudaFuncSetAttribute(attn_tc,    cudaFuncAttributeMaxDynamicSharedMemorySize, ATTN_SMEM);

    dim3 blk(256);

    round_tf32<<<(Mm * Hh / 4 + 255) / 256, blk>>>(x, pxr, Mm * Hh / 4);
    round_tf32<<<(Hh * Hh / 4 + 255) / 256, blk>>>(Wq,  pwr + OFF_WQ,  Hh * Hh / 4);
    round_tf32<<<(Hh * Hh / 4 + 255) / 256, blk>>>(Wk,  pwr + OFF_WK,  Hh * Hh / 4);
    round_tf32<<<(Hh * Hh / 4 + 255) / 256, blk>>>(Wv,  pwr + OFF_WV,  Hh * Hh / 4);
    round_tf32<<<(Hh * Hh / 4 + 255) / 256, blk>>>(Wo,  pwr + OFF_WO,  Hh * Hh / 4);
    round_tf32<<<(Hh * Ee / 4 + 255) / 256, blk>>>(Weq, pwr + OFF_WEQ, Hh * Ee / 4);
    round_tf32<<<(Hh * Ee / 4 + 255) / 256, blk>>>(Wek, pwr + OFF_WEK, Hh * Ee / 4);

    gemm_qkv<<<dim3(Mm / 128, Hh / 128, 3), blk, GEMM_SMEM>>>(pxr, bq, bk, bv);
    gemm_eqk<<<dim3(Mm / 128, Ee / 128, 2), blk, GEMM_SMEM>>>(pxr, beq, bek);
    expbias_tc<<<dim3(Ss / 128, Ss / 128, Bb), blk, EB_SMEM>>>(conf);
    attn_tc<<<dim3(Ss / 128, NH, Bb), blk, ATTN_SMEM>>>();
    gemm_out<<<dim3(Mm / 128, Hh / 128), blk, GEMM_SMEM>>>(pctx, bo, out);
}